// round 12
// baseline (speedup 1.0000x reference)
#include <cuda_runtime.h>
#include <cuda_bf16.h>
#include <cstdint>

#define H 64
#define V 128
#define S 64
#define BATCH 256
#define L 4096

typedef unsigned long long u64;
typedef unsigned int u32;
typedef unsigned short u16;

// Scratch (no allocs allowed)
__device__ float d_hn[V * H];      // LN'd hidden per vocab id
__device__ float d_gTf[S * V];     // gate softmax, transposed [s][v], fp32
__device__ u64   d_Bfrag[64 * 64]; // [p=vpair][h]: lo32 = bf16x2 hi-parts, hi32 = lo
__device__ unsigned g_arr = 0;     // grid barrier arrivals (producers)
__device__ unsigned g_fin = 0;     // end-of-kernel counter (resets g_arr)

__device__ __forceinline__ u32 pack_bf16x2(float lo, float hi) {
    u32 d;
    asm("cvt.rn.bf16x2.f32 %0, %1, %2;" : "=r"(d) : "f"(hi), "f"(lo));
    return d;
}
__device__ __forceinline__ float bflo(u32 p) { return __uint_as_float(p << 16); }
__device__ __forceinline__ float bfhi(u32 p) { return __uint_as_float(p & 0xFFFF0000u); }

__device__ __forceinline__ void mma_bf16(float* c, u32 a0, u32 a1, u32 a2, u32 a3,
                                         u32 b0, u32 b1) {
    asm volatile(
        "mma.sync.aligned.m16n8k16.row.col.f32.bf16.bf16.f32 "
        "{%0,%1,%2,%3}, {%4,%5,%6,%7}, {%8,%9}, {%0,%1,%2,%3};"
        : "+f"(c[0]), "+f"(c[1]), "+f"(c[2]), "+f"(c[3])
        : "r"(a0), "r"(a1), "r"(a2), "r"(a3), "r"(b0), "r"(b1));
}

#define BAR128(id) asm volatile("bar.sync %0, 128;" :: "r"(id) : "memory")

#define BPAD 68

struct FS {
    int sub[8][V];          // 4096 B (hist sub-histograms)
    u64 Bf[64 * BPAD];      // 34816 B
    float skeys[S][BPAD];   // 17408 B (preloaded with slot_keys)
    float cs[V];
    float sq[H];
    float ssim[S];
    float sattn[S];
    float sctx[H];
    float sout[V];
    float wA[2], wB2[2], wC[2];
    // prep-role scratch
    float hs[H];
    float us[2 * H];
    float hns[H];
    float wred[2][2];
};

__global__ void __launch_bounds__(256, 2) fused_kernel(
        const int* __restrict__ seq,
        const float* __restrict__ embed_w,
        const float* __restrict__ w1,
        const float* __restrict__ b1,
        const float* __restrict__ w2,
        const float* __restrict__ b2,
        const float* __restrict__ ln_g,
        const float* __restrict__ ln_b,
        const float* __restrict__ slot_keys,
        const float* __restrict__ gate_w,
        const float* __restrict__ gate_b,
        const float* __restrict__ out_w,
        const float* __restrict__ out_b,
        float* __restrict__ out) {
    extern __shared__ char smraw[];
    FS& sm = *(FS*)smraw;

    int b = blockIdx.x;
    int t = threadIdx.x;
    int lane = t & 31;
    int warp = t >> 5;
    int gid = lane >> 2;
    int tig = lane & 3;

    int qi = seq[b * L + (L - 1)];   // early independent load

    // preload slot_keys into skeys (all 256 threads, 4 float4 each)
    {
        int row = t >> 2;
        int part = (t & 3) * 16;
#pragma unroll
        for (int i = 0; i < 4; i++)
            *(float4*)&sm.skeys[row][part + 4 * i] =
                *(const float4*)&slot_keys[row * H + part + 4 * i];
    }

    // ================= pre-barrier roles =================
    if (b < V) {
        if (t < 128) {
            // ---- prep role: vocab v = b (warps 0-3, bar.sync 1) ----
            int v = b;
            int u = t;
            int ulane = u & 31;
            int uwarp = u >> 5;

            if (u < H) sm.hs[u] = embed_w[v * H + u];
            BAR128(1);

            {
                float a0 = b1[u], a1 = 0.0f;
#pragma unroll
                for (int k = 0; k < H; k += 2) {
                    a0 = fmaf(sm.hs[k],     w1[k * (2 * H) + u],       a0);
                    a1 = fmaf(sm.hs[k + 1], w1[(k + 1) * (2 * H) + u], a1);
                }
                sm.us[u] = fmaxf(a0 + a1, 0.0f);
            }
            BAR128(1);

            float xval = 0.0f;
            if (u < H) {
                float a0 = b2[u], a1 = 0.0f;
#pragma unroll
                for (int k = 0; k < 2 * H; k += 2) {
                    a0 = fmaf(sm.us[k],     w2[k * H + u],       a0);
                    a1 = fmaf(sm.us[k + 1], w2[(k + 1) * H + u], a1);
                }
                xval = sm.hs[u] + a0 + a1;
                float s = xval, sq = xval * xval;
#pragma unroll
                for (int off = 16; off > 0; off >>= 1) {
                    s  += __shfl_xor_sync(0xffffffffu, s, off);
                    sq += __shfl_xor_sync(0xffffffffu, sq, off);
                }
                if (ulane == 0) { sm.wred[uwarp][0] = s; sm.wred[uwarp][1] = sq; }
            }
            BAR128(1);

            if (u < H) {
                float s  = sm.wred[0][0] + sm.wred[1][0];
                float sq = sm.wred[0][1] + sm.wred[1][1];
                float mu = s * (1.0f / H);
                float var = sq * (1.0f / H) - mu * mu;
                float rstd = rsqrtf(var + 1e-5f);
                float val = (xval - mu) * rstd * ln_g[u] + ln_b[u];
                sm.hns[u] = val;
                d_hn[v * H + u] = val;
            }
            BAR128(1);

            float l = 0.0f;
            if (u < S) {
                float a0 = gate_b[u], a1 = 0.0f;
#pragma unroll
                for (int k = 0; k < H; k += 2) {
                    a0 = fmaf(sm.hns[k],     gate_w[k * S + u],       a0);
                    a1 = fmaf(sm.hns[k + 1], gate_w[(k + 1) * S + u], a1);
                }
                l = a0 + a1;
                float m = l;
#pragma unroll
                for (int off = 16; off > 0; off >>= 1)
                    m = fmaxf(m, __shfl_xor_sync(0xffffffffu, m, off));
                if (ulane == 0) sm.wred[uwarp][0] = m;
            }
            BAR128(1);

            float ev = 0.0f;
            if (u < S) {
                float m = fmaxf(sm.wred[0][0], sm.wred[1][0]);
                ev = expf(l - m);
                float ssum = ev;
#pragma unroll
                for (int off = 16; off > 0; off >>= 1)
                    ssum += __shfl_xor_sync(0xffffffffu, ssum, off);
                if (ulane == 0) sm.wred[uwarp][1] = ssum;
            }
            BAR128(1);

            if (u < S) {
                d_gTf[u * V + v] = ev / (sm.wred[0][1] + sm.wred[1][1]);
            } else {
                // u in 64..127: B-fragment halves for h = u-64 (hns final)
                int h = u - 64;
                float x = sm.hns[h];
                __nv_bfloat16 hb = __float2bfloat16(x);
                float hf = __bfloat162float(hb);
                __nv_bfloat16 lb = __float2bfloat16(x - hf);
                int p = v >> 1, par = v & 1;
                u16* q = (u16*)d_Bfrag;
                q[(p * 64 + h) * 4 + par]     = *(u16*)&hb;
                q[(p * 64 + h) * 4 + 2 + par] = *(u16*)&lb;
            }
        } else {
            // ---- hist role: warps 4-7 (bar.sync 2), 4 sub-histograms ----
            int ht = t - 128;
            int hw = warp - 4;
            for (int i = ht; i < 4 * V; i += 128) ((int*)sm.sub)[i] = 0;
            BAR128(2);
            const int4* s4 = (const int4*)(seq + b * L);
            for (int i = ht; i < 1023; i += 128) {
                int4 x = s4[i];
                atomicAdd(&sm.sub[hw][x.x], 1);
                atomicAdd(&sm.sub[hw][x.y], 1);
                atomicAdd(&sm.sub[hw][x.z], 1);
                atomicAdd(&sm.sub[hw][x.w], 1);
            }
            if (ht < 3) atomicAdd(&sm.sub[hw][seq[b * L + 4092 + ht]], 1);
            BAR128(2);
            sm.cs[ht] = (float)(sm.sub[0][ht] + sm.sub[1][ht]
                              + sm.sub[2][ht] + sm.sub[3][ht]);
        }
    } else {
        // ---- blocks 128..255: hist with all 8 warps ----
        for (int i = t; i < 8 * V; i += 256) ((int*)sm.sub)[i] = 0;
        __syncthreads();
        const int4* s4 = (const int4*)(seq + b * L);
        for (int i = t; i < 1023; i += 256) {
            int4 x = s4[i];
            atomicAdd(&sm.sub[warp][x.x], 1);
            atomicAdd(&sm.sub[warp][x.y], 1);
            atomicAdd(&sm.sub[warp][x.z], 1);
            atomicAdd(&sm.sub[warp][x.w], 1);
        }
        if (t < 3) atomicAdd(&sm.sub[warp][seq[b * L + 4092 + t]], 1);
        __syncthreads();
        if (t < V) {
            int tot = 0;
#pragma unroll
            for (int k = 0; k < 8; k++) tot += sm.sub[k][t];
            sm.cs[t] = (float)tot;
        }
    }
    __syncthreads();   // join roles within the block

    // ================= grid barrier =================
    if (b < V && t == 0) {
        __threadfence();
        atomicAdd(&g_arr, 1u);
    }
    if (t == 0) {
        volatile unsigned* p = &g_arr;
        while (*p < (unsigned)V) { __nanosleep(32); }
    }
    __syncthreads();
    __threadfence();

    // ================= post-barrier: MMA + epilogue (R11-proven) =========
    if (t < H) sm.sq[t] = d_hn[qi * H + t];

    // copy B-fragment table into padded smem: 2048 ulonglong2 / 256 threads
#pragma unroll
    for (int i = t; i < 2048; i += 256) {
        int idx = 2 * i;
        int p = idx >> 6, h = idx & 63;
        ulonglong2 w2v = *(const ulonglong2*)&d_Bfrag[p * 64 + h];
        *(ulonglong2*)&sm.Bf[p * BPAD + h] = w2v;
    }
    __syncthreads();

    const int wm = warp & 3;
    const int wn = warp >> 2;
    const int row0 = wm * 16 + gid;

    float acc[4][4];
#pragma unroll
    for (int nt = 0; nt < 4; nt++)
#pragma unroll
        for (int i = 0; i < 4; i++) acc[nt][i] = 0.0f;

    const float* gr0 = d_gTf + row0 * V;
    const float* gr8 = d_gTf + (row0 + 8) * V;

    float2 g0, g1, g2, g3;
    {
        int v0 = 2 * tig, v1 = v0 + 8;
        g0 = *(const float2*)&gr0[v0];
        g1 = *(const float2*)&gr8[v0];
        g2 = *(const float2*)&gr0[v1];
        g3 = *(const float2*)&gr8[v1];
    }
#pragma unroll
    for (int kt = 0; kt < 8; kt++) {
        int pb = kt * 8 + tig;
        int v0 = 2 * pb, v1 = v0 + 8;
        float2 c0 = *(const float2*)&sm.cs[v0];
        float2 c1 = *(const float2*)&sm.cs[v1];
        float p0x = g0.x * c0.x, p0y = g0.y * c0.y;
        float p1x = g1.x * c0.x, p1y = g1.y * c0.y;
        float p2x = g2.x * c1.x, p2y = g2.y * c1.y;
        float p3x = g3.x * c1.x, p3y = g3.y * c1.y;
        if (kt + 1 < 8) {
            int nv0 = v0 + 16, nv1 = v1 + 16;
            g0 = *(const float2*)&gr0[nv0];
            g1 = *(const float2*)&gr8[nv0];
            g2 = *(const float2*)&gr0[nv1];
            g3 = *(const float2*)&gr8[nv1];
        }
        u32 aH0 = pack_bf16x2(p0x, p0y);
        u32 aH1 = pack_bf16x2(p1x, p1y);
        u32 aH2 = pack_bf16x2(p2x, p2y);
        u32 aH3 = pack_bf16x2(p3x, p3y);
        u32 aL0 = pack_bf16x2(p0x - bflo(aH0), p0y - bfhi(aH0));
        u32 aL1 = pack_bf16x2(p1x - bflo(aH1), p1y - bfhi(aH1));
        u32 aL2 = pack_bf16x2(p2x - bflo(aH2), p2y - bfhi(aH2));
        u32 aL3 = pack_bf16x2(p3x - bflo(aH3), p3y - bfhi(aH3));
#pragma unroll
        for (int nt = 0; nt < 4; nt++) {
            int h = (wn * 4 + nt) * 8 + gid;
            u64 B0 = sm.Bf[pb * BPAD + h];
            u64 B1 = sm.Bf[(pb + 4) * BPAD + h];
            u32 bH0 = (u32)B0, bL0 = (u32)(B0 >> 32);
            u32 bH1 = (u32)B1, bL1 = (u32)(B1 >> 32);
            mma_bf16(acc[nt], aH0, aH1, aH2, aH3, bH0, bH1);
            mma_bf16(acc[nt], aH0, aH1, aH2, aH3, bL0, bL1);
            mma_bf16(acc[nt], aL0, aL1, aL2, aL3, bH0, bH1);
        }
    }

    // keys += MMA result (skeys pre-seeded with slot_keys)
#pragma unroll
    for (int nt = 0; nt < 4; nt++) {
        int col = (wn * 4 + nt) * 8 + tig * 2;
        sm.skeys[row0][col]         += acc[nt][0];
        sm.skeys[row0][col + 1]     += acc[nt][1];
        sm.skeys[row0 + 8][col]     += acc[nt][2];
        sm.skeys[row0 + 8][col + 1] += acc[nt][3];
    }

    // q norm (warps 0,1)
    if (t < H) {
        float qv = sm.sq[t];
        float s = qv * qv;
#pragma unroll
        for (int off = 16; off > 0; off >>= 1)
            s += __shfl_xor_sync(0xffffffffu, s, off);
        if (lane == 0) sm.wA[warp] = s;
    }
    __syncthreads();

    // sim: all 8 warps, slot = warp*8+gid, 4-lane h-split
    {
        float qinv = rsqrtf(fmaxf(sm.wA[0] + sm.wA[1], 1e-24f));
        int slot = warp * 8 + gid;
        const float* row = sm.skeys[slot];
        int base = tig * 16;
        float dot = 0.0f, nk = 0.0f;
#pragma unroll
        for (int i = 0; i < 4; i++) {
            float4 kv = *(const float4*)&row[base + 4 * i];
            float4 qv = *(const float4*)&sm.sq[base + 4 * i];
            dot = fmaf(kv.x, qv.x, dot); nk = fmaf(kv.x, kv.x, nk);
            dot = fmaf(kv.y, qv.y, dot); nk = fmaf(kv.y, kv.y, nk);
            dot = fmaf(kv.z, qv.z, dot); nk = fmaf(kv.z, kv.z, nk);
            dot = fmaf(kv.w, qv.w, dot); nk = fmaf(kv.w, kv.w, nk);
        }
        dot += __shfl_xor_sync(0xffffffffu, dot, 1);
        dot += __shfl_xor_sync(0xffffffffu, dot, 2);
        nk  += __shfl_xor_sync(0xffffffffu, nk, 1);
        nk  += __shfl_xor_sync(0xffffffffu, nk, 2);
        if (tig == 0)
            sm.ssim[slot] = dot * qinv / fmaxf(sqrtf(nk), 1e-12f);
    }
    __syncthreads();

    // softmax over 64 (warps 0,1)
    float simv = 0.0f;
    if (t < S) {
        simv = sm.ssim[t];
        float m = simv;
#pragma unroll
        for (int off = 16; off > 0; off >>= 1)
            m = fmaxf(m, __shfl_xor_sync(0xffffffffu, m, off));
        if (lane == 0) sm.wB2[warp] = m;
    }
    __syncthreads();
    float ev = 0.0f;
    if (t < S) {
        float m = fmaxf(sm.wB2[0], sm.wB2[1]);
        ev = expf(simv - m);
        float s = ev;
#pragma unroll
        for (int off = 16; off > 0; off >>= 1)
            s += __shfl_xor_sync(0xffffffffu, s, off);
        if (lane == 0) sm.wC[warp] = s;
    }
    __syncthreads();
    if (t < S) sm.sattn[t] = ev / (sm.wC[0] + sm.wC[1]);
    __syncthreads();

    // ctx: h = t>>2, 4-lane n-split
    {
        int h = t >> 2, sub = t & 3;
        float c = 0.0f;
#pragma unroll
        for (int i = 0; i < 16; i++) {
            int n = sub * 16 + i;
            c = fmaf(sm.sattn[n], sm.skeys[n][h], c);
        }
        c += __shfl_xor_sync(0xffffffffu, c, 1);
        c += __shfl_xor_sync(0xffffffffu, c, 2);
        if (sub == 0) sm.sctx[h] = c;
    }
    __syncthreads();

    // out GEMV: j = t&127, 2-way k-split via smem combine
    {
        int j = t & 127;
        int kh = (t >> 7) * 32;
        float o = 0.0f;
#pragma unroll
        for (int i = 0; i < 32; i++)
            o = fmaf(sm.sctx[kh + i], out_w[(kh + i) * V + j], o);
        if (t >= 128) sm.sout[j] = o;
        __syncthreads();
        if (t < 128) out[b * V + j] = o + sm.sout[j] + out_b[j];
    }

    // ---- reset grid-barrier counters for the next launch/replay ----
    if (t == 0) {
        unsigned o = atomicAdd(&g_fin, 1u);
        if (o == (unsigned)(BATCH - 1)) {
            g_arr = 0;
            g_fin = 0;
            __threadfence();
        }
    }
}

// ---------------------------------------------------------------------------
extern "C" void kernel_launch(void* const* d_in, const int* in_sizes, int n_in,
                              void* d_out, int out_size) {
    const int*   seq       = (const int*)d_in[0];
    const float* embed_w   = (const float*)d_in[1];
    const float* w1        = (const float*)d_in[2];
    const float* b1        = (const float*)d_in[3];
    const float* w2        = (const float*)d_in[4];
    const float* b2        = (const float*)d_in[5];
    const float* ln_g      = (const float*)d_in[6];
    const float* ln_b      = (const float*)d_in[7];
    const float* slot_keys = (const float*)d_in[8];
    // d_in[9] = slot_vals (unused: reference sets vals = keys)
    const float* gate_w    = (const float*)d_in[10];
    const float* gate_b    = (const float*)d_in[11];
    const float* out_w     = (const float*)d_in[12];
    const float* out_b     = (const float*)d_in[13];
    float* out = (float*)d_out;

    int smem_bytes = (int)sizeof(FS);
    cudaFuncSetAttribute(fused_kernel,
                         cudaFuncAttributeMaxDynamicSharedMemorySize, smem_bytes);

    fused_kernel<<<BATCH, 256, smem_bytes>>>(seq, embed_w, w1, b1, w2, b2,
                                             ln_g, ln_b, slot_keys,
                                             gate_w, gate_b, out_w, out_b, out);
}

// round 13
// speedup vs baseline: 1.3790x; 1.3790x over previous
#include <cuda_runtime.h>
#include <cuda_bf16.h>
#include <cstdint>

#define H 64
#define V 128
#define S 64
#define BATCH 256
#define L 4096

typedef unsigned long long u64;
typedef unsigned int u32;
typedef unsigned short u16;

// Scratch (no allocs allowed)
__device__ float d_hn[V * H];      // LN'd hidden per vocab id
__device__ float d_gTf[S * V];     // gate softmax, transposed [s][v], fp32
__device__ u64   d_Bfrag[64 * 64]; // [p=vpair][h]: lo32 = bf16x2 hi-parts, hi32 = lo

__device__ __forceinline__ u32 pack_bf16x2(float lo, float hi) {
    u32 d;
    asm("cvt.rn.bf16x2.f32 %0, %1, %2;" : "=r"(d) : "f"(hi), "f"(lo));
    return d;
}
__device__ __forceinline__ float bflo(u32 p) { return __uint_as_float(p << 16); }
__device__ __forceinline__ float bfhi(u32 p) { return __uint_as_float(p & 0xFFFF0000u); }

__device__ __forceinline__ void mma_bf16(float* c, u32 a0, u32 a1, u32 a2, u32 a3,
                                         u32 b0, u32 b1) {
    asm volatile(
        "mma.sync.aligned.m16n8k16.row.col.f32.bf16.bf16.f32 "
        "{%0,%1,%2,%3}, {%4,%5,%6,%7}, {%8,%9}, {%0,%1,%2,%3};"
        : "+f"(c[0]), "+f"(c[1]), "+f"(c[2]), "+f"(c[3])
        : "r"(a0), "r"(a1), "r"(a2), "r"(a3), "r"(b0), "r"(b1));
}

// ---------------------------------------------------------------------------
// Kernel 1: per-vocab precompute ONLY. grid = V = 128 blocks, 128 threads.
// Emits d_hn, d_gTf (fp32 transposed gate), d_Bfrag (HN hi/lo fragment table).
// ---------------------------------------------------------------------------
__global__ void __launch_bounds__(128) prep_kernel(
        const float* __restrict__ embed_w,
        const float* __restrict__ w1,
        const float* __restrict__ b1,
        const float* __restrict__ w2,
        const float* __restrict__ b2,
        const float* __restrict__ ln_g,
        const float* __restrict__ ln_b,
        const float* __restrict__ gate_w,
        const float* __restrict__ gate_b) {
    int t = threadIdx.x;    // 0..127
    int lane = t & 31;
    int warp = t >> 5;
    int v = blockIdx.x;

    __shared__ float hs[H];
    __shared__ float us[2 * H];
    __shared__ float hns[H];
    __shared__ float wred[2][2];

    if (t < H) hs[t] = embed_w[v * H + t];
    __syncthreads();

    // u = relu(h @ w1 + b1): 128 outputs, dual accumulators
    {
        float a0 = b1[t], a1 = 0.0f;
#pragma unroll
        for (int k = 0; k < H; k += 2) {
            a0 = fmaf(hs[k],     w1[k * (2 * H) + t],       a0);
            a1 = fmaf(hs[k + 1], w1[(k + 1) * (2 * H) + t], a1);
        }
        us[t] = fmaxf(a0 + a1, 0.0f);
    }
    __syncthreads();

    float xval = 0.0f;
    if (t < H) {
        float a0 = b2[t], a1 = 0.0f;
#pragma unroll
        for (int k = 0; k < 2 * H; k += 2) {
            a0 = fmaf(us[k],     w2[k * H + t],       a0);
            a1 = fmaf(us[k + 1], w2[(k + 1) * H + t], a1);
        }
        xval = hs[t] + a0 + a1;
        float s = xval, sq = xval * xval;
#pragma unroll
        for (int off = 16; off > 0; off >>= 1) {
            s  += __shfl_xor_sync(0xffffffffu, s, off);
            sq += __shfl_xor_sync(0xffffffffu, sq, off);
        }
        if (lane == 0) { wred[warp][0] = s; wred[warp][1] = sq; }
    }
    __syncthreads();

    if (t < H) {
        float s  = wred[0][0] + wred[1][0];
        float sq = wred[0][1] + wred[1][1];
        float mu = s * (1.0f / H);
        float var = sq * (1.0f / H) - mu * mu;
        float rstd = rsqrtf(var + 1e-5f);
        float val = (xval - mu) * rstd * ln_g[t] + ln_b[t];
        hns[t] = val;
        d_hn[v * H + t] = val;
    }
    __syncthreads();

    float l = 0.0f;
    if (t < S) {
        float a0 = gate_b[t], a1 = 0.0f;
#pragma unroll
        for (int k = 0; k < H; k += 2) {
            a0 = fmaf(hns[k],     gate_w[k * S + t],       a0);
            a1 = fmaf(hns[k + 1], gate_w[(k + 1) * S + t], a1);
        }
        l = a0 + a1;
        float m = l;
#pragma unroll
        for (int off = 16; off > 0; off >>= 1)
            m = fmaxf(m, __shfl_xor_sync(0xffffffffu, m, off));
        if (lane == 0) wred[warp][0] = m;
    }
    __syncthreads();

    float ev = 0.0f;
    if (t < S) {
        float m = fmaxf(wred[0][0], wred[1][0]);
        ev = expf(l - m);
        float ssum = ev;
#pragma unroll
        for (int off = 16; off > 0; off >>= 1)
            ssum += __shfl_xor_sync(0xffffffffu, ssum, off);
        if (lane == 0) wred[warp][1] = ssum;
    }
    __syncthreads();

    if (t < S) {
        d_gTf[t * V + v] = ev / (wred[0][1] + wred[1][1]);
    } else {
        // threads 64..127: B-fragment halves for h = t-64 (hns is final)
        int h = t - 64;
        float x = hns[h];
        __nv_bfloat16 hb = __float2bfloat16(x);
        float hf = __bfloat162float(hb);
        __nv_bfloat16 lb = __float2bfloat16(x - hf);
        int p = v >> 1, par = v & 1;
        u16* q = (u16*)d_Bfrag;
        q[(p * 64 + h) * 4 + par]     = *(u16*)&hb;
        q[(p * 64 + h) * 4 + 2 + par] = *(u16*)&lb;
    }
}

// ---------------------------------------------------------------------------
// Kernel 2: one batch per block, 256 threads = 8 warps.
// In-block hist; B table copied verbatim to smem (issued before hist atomics);
// A' = gate*cnt built in registers (hi/lo); R11 MMA + parallel epilogue.
// ---------------------------------------------------------------------------
#define BPAD 68

struct FinalSmem {
    int sub[8][V];          // 4096 B
    u64 Bf[64 * BPAD];      // 34816 B
    float skeys[S][BPAD];   // 17408 B
    float cs[V];
    float sq[H];
    float ssim[S];
    float sattn[S];
    float sctx[H];
    float sout[V];
    float wA[2], wB2[2], wC[2];
};

__global__ void __launch_bounds__(256, 2) final_kernel(
        const int* __restrict__ seq,
        const float* __restrict__ slot_keys,
        const float* __restrict__ out_w,
        const float* __restrict__ out_b,
        float* __restrict__ out) {
    extern __shared__ char smraw[];
    FinalSmem& sm = *(FinalSmem*)smraw;

    int b = blockIdx.x;
    int t = threadIdx.x;
    int lane = t & 31;
    int warp = t >> 5;
    int gid = lane >> 2;
    int tig = lane & 3;

    int qi = seq[b * L + (L - 1)];   // early independent load

    // zero hist sub-arrays
    for (int i = t; i < 8 * V; i += 256) ((int*)sm.sub)[i] = 0;
    __syncthreads();

    // B-table copy (independent of hist; warps interleave it with hist below)
#pragma unroll
    for (int i = t; i < 2048; i += 256) {
        int idx = 2 * i;
        int p = idx >> 6, h = idx & 63;
        ulonglong2 w2v = *(const ulonglong2*)&d_Bfrag[p * 64 + h];
        *(ulonglong2*)&sm.Bf[p * BPAD + h] = w2v;
    }
    // q into smem (d_hn resident in L2 from prep)
    if (t < H) sm.sq[t] = d_hn[qi * H + t];

    // hist of seq[b, 0:4095]
    {
        const int4* s4 = (const int4*)(seq + b * L);
        for (int i = t; i < 1023; i += 256) {
            int4 x = s4[i];
            atomicAdd(&sm.sub[warp][x.x], 1);
            atomicAdd(&sm.sub[warp][x.y], 1);
            atomicAdd(&sm.sub[warp][x.z], 1);
            atomicAdd(&sm.sub[warp][x.w], 1);
        }
        if (t < 3) atomicAdd(&sm.sub[warp][seq[b * L + 4092 + t]], 1);
    }
    __syncthreads();
    if (t < V) {
        int tot = 0;
#pragma unroll
        for (int k = 0; k < 8; k++) tot += sm.sub[k][t];
        sm.cs[t] = (float)tot;
    }
    __syncthreads();

    // ---- MMA: warp (wm = w&3, wn = w>>2); A' in regs, B via padded LDS ----
    const int wm = warp & 3;
    const int wn = warp >> 2;
    const int row0 = wm * 16 + gid;

    float acc[4][4];
#pragma unroll
    for (int nt = 0; nt < 4; nt++)
#pragma unroll
        for (int i = 0; i < 4; i++) acc[nt][i] = 0.0f;

    const float* gr0 = d_gTf + row0 * V;
    const float* gr8 = d_gTf + (row0 + 8) * V;

    float2 g0, g1, g2, g3;
    {
        int v0 = 2 * tig, v1 = v0 + 8;
        g0 = *(const float2*)&gr0[v0];
        g1 = *(const float2*)&gr8[v0];
        g2 = *(const float2*)&gr0[v1];
        g3 = *(const float2*)&gr8[v1];
    }
#pragma unroll
    for (int kt = 0; kt < 8; kt++) {
        int pb = kt * 8 + tig;
        int v0 = 2 * pb, v1 = v0 + 8;
        float2 c0 = *(const float2*)&sm.cs[v0];
        float2 c1 = *(const float2*)&sm.cs[v1];
        float p0x = g0.x * c0.x, p0y = g0.y * c0.y;
        float p1x = g1.x * c0.x, p1y = g1.y * c0.y;
        float p2x = g2.x * c1.x, p2y = g2.y * c1.y;
        float p3x = g3.x * c1.x, p3y = g3.y * c1.y;
        if (kt + 1 < 8) {
            int nv0 = v0 + 16, nv1 = v1 + 16;
            g0 = *(const float2*)&gr0[nv0];
            g1 = *(const float2*)&gr8[nv0];
            g2 = *(const float2*)&gr0[nv1];
            g3 = *(const float2*)&gr8[nv1];
        }
        u32 aH0 = pack_bf16x2(p0x, p0y);
        u32 aH1 = pack_bf16x2(p1x, p1y);
        u32 aH2 = pack_bf16x2(p2x, p2y);
        u32 aH3 = pack_bf16x2(p3x, p3y);
        u32 aL0 = pack_bf16x2(p0x - bflo(aH0), p0y - bfhi(aH0));
        u32 aL1 = pack_bf16x2(p1x - bflo(aH1), p1y - bfhi(aH1));
        u32 aL2 = pack_bf16x2(p2x - bflo(aH2), p2y - bfhi(aH2));
        u32 aL3 = pack_bf16x2(p3x - bflo(aH3), p3y - bfhi(aH3));
#pragma unroll
        for (int nt = 0; nt < 4; nt++) {
            int h = (wn * 4 + nt) * 8 + gid;
            u64 B0 = sm.Bf[pb * BPAD + h];
            u64 B1 = sm.Bf[(pb + 4) * BPAD + h];
            u32 bH0 = (u32)B0, bL0 = (u32)(B0 >> 32);
            u32 bH1 = (u32)B1, bL1 = (u32)(B1 >> 32);
            mma_bf16(acc[nt], aH0, aH1, aH2, aH3, bH0, bH1);
            mma_bf16(acc[nt], aH0, aH1, aH2, aH3, bL0, bL1);
            mma_bf16(acc[nt], aL0, aL1, aL2, aL3, bH0, bH1);
        }
    }

    // keys (+ slot_keys) -> shared
#pragma unroll
    for (int nt = 0; nt < 4; nt++) {
        int col = (wn * 4 + nt) * 8 + tig * 2;
        float2 sk0 = *(const float2*)&slot_keys[row0 * H + col];
        float2 sk1 = *(const float2*)&slot_keys[(row0 + 8) * H + col];
        sm.skeys[row0][col]         = acc[nt][0] + sk0.x;
        sm.skeys[row0][col + 1]     = acc[nt][1] + sk0.y;
        sm.skeys[row0 + 8][col]     = acc[nt][2] + sk1.x;
        sm.skeys[row0 + 8][col + 1] = acc[nt][3] + sk1.y;
    }

    // q norm (warps 0,1)
    if (t < H) {
        float qv = sm.sq[t];
        float s = qv * qv;
#pragma unroll
        for (int off = 16; off > 0; off >>= 1)
            s += __shfl_xor_sync(0xffffffffu, s, off);
        if (lane == 0) sm.wA[warp] = s;
    }
    __syncthreads();

    // sim: all 8 warps, slot = warp*8+gid, 4-lane h-split
    {
        float qinv = rsqrtf(fmaxf(sm.wA[0] + sm.wA[1], 1e-24f));
        int slot = warp * 8 + gid;
        const float* row = sm.skeys[slot];
        int base = tig * 16;
        float dot = 0.0f, nk = 0.0f;
#pragma unroll
        for (int i = 0; i < 4; i++) {
            float4 kv = *(const float4*)&row[base + 4 * i];
            float4 qv = *(const float4*)&sm.sq[base + 4 * i];
            dot = fmaf(kv.x, qv.x, dot); nk = fmaf(kv.x, kv.x, nk);
            dot = fmaf(kv.y, qv.y, dot); nk = fmaf(kv.y, kv.y, nk);
            dot = fmaf(kv.z, qv.z, dot); nk = fmaf(kv.z, kv.z, nk);
            dot = fmaf(kv.w, qv.w, dot); nk = fmaf(kv.w, kv.w, nk);
        }
        dot += __shfl_xor_sync(0xffffffffu, dot, 1);
        dot += __shfl_xor_sync(0xffffffffu, dot, 2);
        nk  += __shfl_xor_sync(0xffffffffu, nk, 1);
        nk  += __shfl_xor_sync(0xffffffffu, nk, 2);
        if (tig == 0)
            sm.ssim[slot] = dot * qinv / fmaxf(sqrtf(nk), 1e-12f);
    }
    __syncthreads();

    // softmax over 64 (warps 0,1)
    float simv = 0.0f;
    if (t < S) {
        simv = sm.ssim[t];
        float m = simv;
#pragma unroll
        for (int off = 16; off > 0; off >>= 1)
            m = fmaxf(m, __shfl_xor_sync(0xffffffffu, m, off));
        if (lane == 0) sm.wB2[warp] = m;
    }
    __syncthreads();
    float ev = 0.0f;
    if (t < S) {
        float m = fmaxf(sm.wB2[0], sm.wB2[1]);
        ev = expf(simv - m);
        float s = ev;
#pragma unroll
        for (int off = 16; off > 0; off >>= 1)
            s += __shfl_xor_sync(0xffffffffu, s, off);
        if (lane == 0) sm.wC[warp] = s;
    }
    __syncthreads();
    if (t < S) sm.sattn[t] = ev / (sm.wC[0] + sm.wC[1]);
    __syncthreads();

    // ctx: h = t>>2, 4-lane n-split
    {
        int h = t >> 2, sub = t & 3;
        float c = 0.0f;
#pragma unroll
        for (int i = 0; i < 16; i++) {
            int n = sub * 16 + i;
            c = fmaf(sm.sattn[n], sm.skeys[n][h], c);
        }
        c += __shfl_xor_sync(0xffffffffu, c, 1);
        c += __shfl_xor_sync(0xffffffffu, c, 2);
        if (sub == 0) sm.sctx[h] = c;
    }
    __syncthreads();

    // out GEMV: j = t&127, 2-way k-split via smem combine
    {
        int j = t & 127;
        int kh = (t >> 7) * 32;
        float o = 0.0f;
#pragma unroll
        for (int i = 0; i < 32; i++)
            o = fmaf(sm.sctx[kh + i], out_w[(kh + i) * V + j], o);
        if (t >= 128) sm.sout[j] = o;
        __syncthreads();
        if (t < 128) out[b * V + j] = o + sm.sout[j] + out_b[j];
    }
}

// ---------------------------------------------------------------------------
extern "C" void kernel_launch(void* const* d_in, const int* in_sizes, int n_in,
                              void* d_out, int out_size) {
    const int*   seq       = (const int*)d_in[0];
    const float* embed_w   = (const float*)d_in[1];
    const float* w1        = (const float*)d_in[2];
    const float* b1        = (const float*)d_in[3];
    const float* w2        = (const float*)d_in[4];
    const float* b2        = (const float*)d_in[5];
    const float* ln_g      = (const float*)d_in[6];
    const float* ln_b      = (const float*)d_in[7];
    const float* slot_keys = (const float*)d_in[8];
    // d_in[9] = slot_vals (unused: reference sets vals = keys)
    const float* gate_w    = (const float*)d_in[10];
    const float* gate_b    = (const float*)d_in[11];
    const float* out_w     = (const float*)d_in[12];
    const float* out_b     = (const float*)d_in[13];
    float* out = (float*)d_out;

    int smem_bytes = (int)sizeof(FinalSmem);
    cudaFuncSetAttribute(final_kernel,
                         cudaFuncAttributeMaxDynamicSharedMemorySize, smem_bytes);

    prep_kernel<<<V, 128>>>(embed_w, w1, b1, w2, b2, ln_g, ln_b, gate_w, gate_b);
    final_kernel<<<BATCH, 256, smem_bytes>>>(seq, slot_keys, out_w, out_b, out);
}